// round 2
// baseline (speedup 1.0000x reference)
#include <cuda_runtime.h>
#include <cstdint>

// Problem constants
#define BATCH 16
#define CDIM  64
#define HW    4096            // 64*64
#define NROWS 65536           // B*H*W
#define KCODES 512
#define OUT_ELEMS 4194304     // B*C*H*W
#define LOSS_OFS  4194304
#define PERP_OFS  4194305
#define ACT_OFS   4194306
#define IDX_OFS   4194307

#define MAIN_BLOCKS 148
#define MAIN_THREADS 448
#define ROWS_PER_BLOCK 443    // ceil(65536/148)

__device__ int   g_hist[KCODES];        // zero-initialized at load; re-zeroed by finalize
__device__ float g_partial[MAIN_BLOCKS];

typedef unsigned long long ull;

__device__ __forceinline__ ull pack2(float lo, float hi) {
    ull r; asm("mov.b64 %0, {%1, %2};" : "=l"(r) : "f"(lo), "f"(hi)); return r;
}
__device__ __forceinline__ void unpack2(ull v, float& lo, float& hi) {
    asm("mov.b64 {%0, %1}, %2;" : "=f"(lo), "=f"(hi) : "l"(v));
}
__device__ __forceinline__ ull fma2(ull a, ull b, ull c) {
    ull d; asm("fma.rn.f32x2 %0, %1, %2, %3;" : "=l"(d) : "l"(a), "l"(b), "l"(c)); return d;
}
__device__ __forceinline__ ull add2(ull a, ull b) {
    ull d; asm("add.rn.f32x2 %0, %1, %2;" : "=l"(d) : "l"(a), "l"(b)); return d;
}

__global__ void vq_dummy() {}

// ---------------- main: distances, argmin, quantized output, hist, commit ----------------
__global__ __launch_bounds__(MAIN_THREADS, 1)
void vq_main(const float* __restrict__ x, const float* __restrict__ emb,
             float* __restrict__ d_out) {
    extern __shared__ float sm[];
    float* se    = sm;                       // [512][64] codebook (unpadded)
    float* sssq  = sm + KCODES * CDIM;       // [512]
    int*   shist = (int*)(sssq + KCODES);    // [512]
    float* sred  = (float*)(shist + KCODES); // [512] (padded for 448-thread tree)

    const int tid = threadIdx.x;

    // load codebook into smem (float4, coalesced)
    for (int i = tid; i < KCODES * (CDIM / 4); i += MAIN_THREADS) {
        ((float4*)se)[i] = ((const float4*)emb)[i];
    }
    for (int i = tid; i < KCODES; i += MAIN_THREADS) shist[i] = 0;
    if (tid < 64) sred[MAIN_THREADS + tid] = 0.f;   // pad reduction tail
    __syncthreads();

    // per-block ssq from smem with lane-rotation (bank-conflict free)
    for (int r = tid; r < KCODES; r += MAIN_THREADS) {
        const float* row = se + r * CDIM;
        float s = 0.f;
        const int rot = tid & 31;
#pragma unroll
        for (int c = 0; c < CDIM; ++c) {
            float v = row[(c + rot) & (CDIM - 1)];
            s = fmaf(v, v, s);
        }
        sssq[r] = s;
    }
    __syncthreads();

    // one row per thread
    const int nrows_blk = min(NROWS - blockIdx.x * ROWS_PER_BLOCK, ROWS_PER_BLOCK);
    const bool active = tid < nrows_blk;
    const int rowRaw = blockIdx.x * ROWS_PER_BLOCK + tid;
    const int row = active ? rowRaw : 0;
    const int b  = row >> 12, hw = row & 4095;
    const float* p = x + ((long)b << 18) + hw;     // b*64*4096 + hw

    ull X[32];
#pragma unroll
    for (int j = 0; j < 32; ++j)
        X[j] = pack2(p[(2 * j) * HW], p[(2 * j + 1) * HW]);

    float best = 3.4e38f;
    int bi = 0;

    for (int k = 0; k < KCODES; ++k) {
        const ulonglong2* ep = (const ulonglong2*)(se + (k << 6));
        ull a0 = 0, a1 = 0;
#pragma unroll
        for (int j = 0; j < 16; ++j) {
            ulonglong2 e = ep[j];
            a0 = fma2(X[2 * j],     e.x, a0);
            a1 = fma2(X[2 * j + 1], e.y, a1);
        }
        a0 = add2(a0, a1);
        float lo, hi;
        unpack2(a0, lo, hi);
        const float s = fmaf(-2.f, lo + hi, sssq[k]);
        if (s < best) { best = s; bi = k; }
    }

    // epilogue: gather code, write quantized output, commitment, histogram, index
    float csum = 0.f;
    if (active) {
        float* op = d_out + ((long)b << 18) + hw;
        const float* er = se + (bi << 6);
#pragma unroll
        for (int j = 0; j < 32; ++j) {
            float xl, xh;
            unpack2(X[j], xl, xh);
            float e0 = er[2 * j], e1 = er[2 * j + 1];
            float d0 = xl - e0, d1 = xh - e1;
            csum += d0 * d0 + d1 * d1;
            op[(2 * j) * HW]     = e0;
            op[(2 * j + 1) * HW] = e1;
        }
        d_out[IDX_OFS + row] = (float)bi;
        atomicAdd(&shist[bi], 1);
    }

    // deterministic block reduction of commitment partial (tree over 512 slots)
    sred[tid] = csum;
    __syncthreads();
#pragma unroll
    for (int s = 256; s > 0; s >>= 1) {
        if (tid < s) sred[tid] += sred[tid + s];
        __syncthreads();
    }
    if (tid == 0) g_partial[blockIdx.x] = sred[0];

    // merge histogram into global
    for (int i = tid; i < KCODES; i += MAIN_THREADS) {
        int c = shist[i];
        if (c) atomicAdd(&g_hist[i], c);
    }
}

// ---------------- finalize: perplexity, loss, active codes; re-zero hist ----------------
__global__ void vq_finalize(const float* __restrict__ weight, float* __restrict__ d_out) {
    __shared__ float rf[KCODES];
    __shared__ int   ri[KCODES];
    int k = threadIdx.x;
    int h = g_hist[k];
    g_hist[k] = 0;   // reset for next graph replay (deterministic)
    float p = (float)h * (1.f / (float)NROWS);
    rf[k] = p * logf(p + 1e-10f);
    ri[k] = (weight[k] >= 0.01f) ? 1 : 0;
    __syncthreads();
#pragma unroll
    for (int s = 256; s > 0; s >>= 1) {
        if (k < s) { rf[k] += rf[k + s]; ri[k] += ri[k + s]; }
        __syncthreads();
    }
    if (k == 0) {
        float s = 0.f;
        for (int i = 0; i < MAIN_BLOCKS; ++i) s += g_partial[i];  // fixed order
        d_out[LOSS_OFS] = s * (1.f / ((float)NROWS * (float)CDIM));
        d_out[PERP_OFS] = expf(-rf[0]);
        d_out[ACT_OFS]  = (float)ri[0];
    }
}

extern "C" void kernel_launch(void* const* d_in, const int* in_sizes, int n_in,
                              void* d_out, int out_size) {
    const float* x      = (const float*)d_in[0];  // [B,C,H,W]
    const float* emb    = (const float*)d_in[1];  // [K,C]
    const float* weight = (const float*)d_in[2];  // [K]
    float* out = (float*)d_out;

    static bool attr_set = false;
    const int smem = (KCODES * CDIM + KCODES + KCODES + 512) * 4;
    if (!attr_set) {
        cudaFuncSetAttribute(vq_main, cudaFuncAttributeMaxDynamicSharedMemorySize, smem);
        attr_set = true;
    }

    // 4 launches/call so ncu (-s 5 -c 1) profiles vq_main (global launch #5)
    vq_dummy<<<1, 32>>>();
    vq_main<<<MAIN_BLOCKS, MAIN_THREADS, smem>>>(x, emb, out);
    vq_finalize<<<1, KCODES>>>(weight, out);
    vq_dummy<<<1, 32>>>();
}

// round 3
// speedup vs baseline: 1.1460x; 1.1460x over previous
#include <cuda_runtime.h>
#include <cstdint>

// Problem constants
#define CDIM  64
#define HW    4096            // 64*64
#define NROWS 65536           // B*H*W
#define KCODES 512
#define ROWPAD 68             // padded smem row stride (floats)
#define LOSS_OFS  4194304
#define PERP_OFS  4194305
#define ACT_OFS   4194306
#define IDX_OFS   4194307

#define MAIN_BLOCKS 128
#define MAIN_THREADS 256
// each block: 512 rows (2 per thread)

__device__ int          g_hist[KCODES];      // zero at load; re-zeroed by last block
__device__ float        g_partial[MAIN_BLOCKS];
__device__ unsigned int g_done;              // zero at load; reset by last block

typedef unsigned long long ull;

__device__ __forceinline__ ull pack2(float lo, float hi) {
    ull r; asm("mov.b64 %0, {%1, %2};" : "=l"(r) : "f"(lo), "f"(hi)); return r;
}
__device__ __forceinline__ void unpack2(ull v, float& lo, float& hi) {
    asm("mov.b64 {%0, %1}, %2;" : "=f"(lo), "=f"(hi) : "l"(v));
}
__device__ __forceinline__ ull fma2(ull a, ull b, ull c) {
    ull d; asm("fma.rn.f32x2 %0, %1, %2, %3;" : "=l"(d) : "l"(a), "l"(b), "l"(c)); return d;
}
__device__ __forceinline__ ull add2(ull a, ull b) {
    ull d; asm("add.rn.f32x2 %0, %1, %2;" : "=l"(d) : "l"(a), "l"(b)); return d;
}

// ---------------- single fused kernel ----------------
__global__ __launch_bounds__(MAIN_THREADS, 1)
void vq_fused(const float* __restrict__ x, const float* __restrict__ emb,
              const float* __restrict__ weight, float* __restrict__ d_out) {
    extern __shared__ float sm[];
    float* se    = sm;                       // [512][68] padded codebook
    float* sssq  = sm + KCODES * ROWPAD;     // [512]
    int*   shist = (int*)(sssq + KCODES);    // [512]
    float* sred  = (float*)(shist + KCODES); // [256]
    __shared__ unsigned int s_last;

    const int tid = threadIdx.x;

    // load codebook into padded smem (float4, coalesced) + zero local hist
    for (int i = tid; i < KCODES * (CDIM / 4); i += MAIN_THREADS) {
        int r = i >> 4, q = i & 15;
        ((float4*)(se + r * ROWPAD))[q] = ((const float4*)emb)[i];
    }
    for (int i = tid; i < KCODES; i += MAIN_THREADS) shist[i] = 0;
    __syncthreads();

    // per-block ssq via lane rotation (conflict-free: stride 68, banks distinct)
    for (int r = tid; r < KCODES; r += MAIN_THREADS) {
        const float* row = se + r * ROWPAD;
        float s = 0.f;
        const int rot = tid & 31;
#pragma unroll
        for (int c = 0; c < CDIM; ++c) {
            float v = row[(c + rot) & (CDIM - 1)];
            s = fmaf(v, v, s);
        }
        sssq[r] = s;
    }
    __syncthreads();

    // two rows per thread
    const int r0 = blockIdx.x * 512 + tid;
    const int r1 = r0 + 256;
    const int b0 = r0 >> 12, hw0 = r0 & 4095;
    const int b1 = r1 >> 12, hw1 = r1 & 4095;
    const float* p0 = x + ((long)b0 << 18) + hw0;   // b*64*4096
    const float* p1 = x + ((long)b1 << 18) + hw1;

    ull Xa[32], Xb[32];
#pragma unroll
    for (int j = 0; j < 32; ++j) {
        Xa[j] = pack2(p0[(2 * j) * HW], p0[(2 * j + 1) * HW]);
        Xb[j] = pack2(p1[(2 * j) * HW], p1[(2 * j + 1) * HW]);
    }

    float bestA = 3.4e38f, bestB = 3.4e38f;
    int biA = 0, biB = 0;

    for (int k = 0; k < KCODES; ++k) {
        const ulonglong2* ep = (const ulonglong2*)(se + k * ROWPAD);
        ull a0 = 0, a1 = 0, a2 = 0, a3 = 0;
        ull c0 = 0, c1 = 0, c2 = 0, c3 = 0;
#pragma unroll
        for (int j = 0; j < 16; ++j) {
            ulonglong2 e = ep[j];
            if (j & 1) {
                a2 = fma2(Xa[2 * j],     e.x, a2);
                a3 = fma2(Xa[2 * j + 1], e.y, a3);
                c2 = fma2(Xb[2 * j],     e.x, c2);
                c3 = fma2(Xb[2 * j + 1], e.y, c3);
            } else {
                a0 = fma2(Xa[2 * j],     e.x, a0);
                a1 = fma2(Xa[2 * j + 1], e.y, a1);
                c0 = fma2(Xb[2 * j],     e.x, c0);
                c1 = fma2(Xb[2 * j + 1], e.y, c1);
            }
        }
        a0 = add2(add2(a0, a1), add2(a2, a3));
        c0 = add2(add2(c0, c1), add2(c2, c3));
        float alo, ahi, clo, chi;
        unpack2(a0, alo, ahi);
        unpack2(c0, clo, chi);
        const float sq = sssq[k];
        const float sA = fmaf(-2.f, alo + ahi, sq);
        const float sB = fmaf(-2.f, clo + chi, sq);
        if (sA < bestA) { bestA = sA; biA = k; }
        if (sB < bestB) { bestB = sB; biB = k; }
    }

    // epilogue: gather codes, write quantized output, commitment, histogram, indices
    float csum = 0.f;
    {
        float* op = d_out + ((long)b0 << 18) + hw0;
        const float* er = se + biA * ROWPAD;
#pragma unroll
        for (int j = 0; j < 32; ++j) {
            float xl, xh;
            unpack2(Xa[j], xl, xh);
            float e0 = er[2 * j], e1 = er[2 * j + 1];
            float d0 = xl - e0, d1 = xh - e1;
            csum += d0 * d0 + d1 * d1;
            op[(2 * j) * HW]     = e0;
            op[(2 * j + 1) * HW] = e1;
        }
        d_out[IDX_OFS + r0] = (float)biA;
        atomicAdd(&shist[biA], 1);
    }
    {
        float* op = d_out + ((long)b1 << 18) + hw1;
        const float* er = se + biB * ROWPAD;
#pragma unroll
        for (int j = 0; j < 32; ++j) {
            float xl, xh;
            unpack2(Xb[j], xl, xh);
            float e0 = er[2 * j], e1 = er[2 * j + 1];
            float d0 = xl - e0, d1 = xh - e1;
            csum += d0 * d0 + d1 * d1;
            op[(2 * j) * HW]     = e0;
            op[(2 * j + 1) * HW] = e1;
        }
        d_out[IDX_OFS + r1] = (float)biB;
        atomicAdd(&shist[biB], 1);
    }

    // deterministic block reduction of commitment partial
    sred[tid] = csum;
    __syncthreads();
#pragma unroll
    for (int s = 128; s > 0; s >>= 1) {
        if (tid < s) sred[tid] += sred[tid + s];
        __syncthreads();
    }
    if (tid == 0) g_partial[blockIdx.x] = sred[0];

    // merge histogram into global
    for (int i = tid; i < KCODES; i += MAIN_THREADS) {
        int c = shist[i];
        if (c) atomicAdd(&g_hist[i], c);
    }

    // ---- last-block finalize (fused, deterministic) ----
    __threadfence();
    __syncthreads();
    if (tid == 0) {
        unsigned int v = atomicAdd(&g_done, 1u);
        s_last = (v == MAIN_BLOCKS - 1) ? 1u : 0u;
    }
    __syncthreads();
    if (s_last) {
        __threadfence();  // acquire all blocks' g_partial / g_hist writes
        // perplexity term + active codes: each thread covers 2 of 512
        int   h0 = g_hist[tid], h1 = g_hist[tid + 256];
        float q0 = (float)h0 * (1.f / (float)NROWS);
        float q1 = (float)h1 * (1.f / (float)NROWS);
        float plog = q0 * logf(q0 + 1e-10f) + q1 * logf(q1 + 1e-10f);
        int   act  = (weight[tid] >= 0.01f ? 1 : 0) + (weight[tid + 256] >= 0.01f ? 1 : 0);
        // reset globals for next graph replay
        g_hist[tid]       = 0;
        g_hist[tid + 256] = 0;
        sred[tid]  = plog;
        shist[tid] = act;
        __syncthreads();
#pragma unroll
        for (int s = 128; s > 0; s >>= 1) {
            if (tid < s) { sred[tid] += sred[tid + s]; shist[tid] += shist[tid + s]; }
            __syncthreads();
        }
        if (tid == 0) {
            float s = 0.f;
            for (int i = 0; i < MAIN_BLOCKS; ++i) s += g_partial[i];  // fixed order
            d_out[LOSS_OFS] = s * (1.f / ((float)NROWS * (float)CDIM));
            d_out[PERP_OFS] = expf(-sred[0]);
            d_out[ACT_OFS]  = (float)shist[0];
            g_done = 0;  // reset for next replay
        }
    }
}

extern "C" void kernel_launch(void* const* d_in, const int* in_sizes, int n_in,
                              void* d_out, int out_size) {
    const float* x      = (const float*)d_in[0];  // [B,C,H,W]
    const float* emb    = (const float*)d_in[1];  // [K,C]
    const float* weight = (const float*)d_in[2];  // [K]
    float* out = (float*)d_out;

    static bool attr_set = false;
    const int smem = (KCODES * ROWPAD + KCODES + KCODES + MAIN_THREADS) * 4;
    if (!attr_set) {
        cudaFuncSetAttribute(vq_fused, cudaFuncAttributeMaxDynamicSharedMemorySize, smem);
        attr_set = true;
    }

    vq_fused<<<MAIN_BLOCKS, MAIN_THREADS, smem>>>(x, emb, weight, out);
}